// round 11
// baseline (speedup 1.0000x reference)
#include <cuda_runtime.h>
#include <cuda_fp16.h>
#include <cstdint>

// ---------------- problem constants ----------------
#define BATCH     4
#define SEQLEN    4096
#define NTOK      (BATCH * SEQLEN)      // 16384
#define DMODEL    1024
#define EVDIM     16
#define DIN       2048                  // d_inner
#define NHEADS    32
#define DSTATE    64
#define HEADDIM   64
#define DCONV     4
#define BLK       16                    // block_len
#define NCHUNK    (SEQLEN / BLK)        // 256
#define KAUG      1088                  // 1040 padded to multiple of 64
#define NBC       4224                  // 2048 B + 2048 C + 32 dt + 96 pad

// ---------------- scratch (device globals; no runtime allocation) ----------
__device__ __half g_augh [ (size_t)NTOK * KAUG ];    // [x | ev | 0pad] (half)
__device__ __half g_winth[ (size_t)4096 * KAUG ];    // in_proj_w^T (half)
__device__ __half g_wbcth[ (size_t)NBC * DIN ];      // [w_B^T ; w_C^T ; w_dt^T ; 0]
__device__ __half g_woth [ (size_t)DMODEL * DIN ];   // out_proj_w^T (half)
__device__ __half g_xzh  [ (size_t)NTOK * 2 * DIN ]; // x_path | z (half)
__device__ __half g_xch  [ (size_t)NTOK * DIN ];     // conv+silu out (half)
__device__ __half g_BCh  [ (size_t)NTOK * NBC ];     // [B | C | dtraw | pad] (half)
__device__ __half g_Yzh  [ (size_t)NTOK * DIN ];     // Y*silu(z) (half)
__device__ float  g_A    [ (size_t)NTOK * NHEADS ];
__device__ float  g_out  [ (size_t)NTOK * DMODEL ];  // pre-LN (f32)

// ================= helpers =================================================
__device__ __forceinline__ uint32_t smem_u32(const void* p) {
    uint32_t a;
    asm("{ .reg .u64 t; cvta.to.shared.u64 t, %1; cvt.u32.u64 %0, t; }"
        : "=r"(a) : "l"(p));
    return a;
}
__device__ __forceinline__ void cp16(uint32_t s, const void* g) {
    asm volatile("cp.async.cg.shared.global [%0], [%1], 16;\n" :: "r"(s), "l"(g));
}
__device__ __forceinline__ void cp4(uint32_t s, const void* g) {
    asm volatile("cp.async.ca.shared.global [%0], [%1], 4;\n" :: "r"(s), "l"(g));
}
__device__ __forceinline__ void cp_commit() { asm volatile("cp.async.commit_group;\n" ::); }
template<int N> __device__ __forceinline__ void cp_wait() {
    asm volatile("cp.async.wait_group %0;\n" :: "n"(N));
}
__device__ __forceinline__ void ldm4(uint32_t* r, uint32_t addr) {
    asm volatile("ldmatrix.sync.aligned.m8n8.x4.shared.b16 {%0,%1,%2,%3}, [%4];"
        : "=r"(r[0]), "=r"(r[1]), "=r"(r[2]), "=r"(r[3]) : "r"(addr));
}
__device__ __forceinline__ void mma16(float* c, const uint32_t* a, const uint32_t* b) {
    asm volatile(
        "mma.sync.aligned.m16n8k16.row.col.f32.f16.f16.f32 "
        "{%0,%1,%2,%3}, {%4,%5,%6,%7}, {%8,%9}, {%0,%1,%2,%3};"
        : "+f"(c[0]), "+f"(c[1]), "+f"(c[2]), "+f"(c[3])
        : "r"(a[0]), "r"(a[1]), "r"(a[2]), "r"(a[3]), "r"(b[0]), "r"(b[1]));
}
__device__ __forceinline__ float silu_f(float z) { return z / (1.f + __expf(-z)); }

// ================= fp16 warp-MMA GEMM (R9 proven: 2-stage, 2 CTAs/SM) ======
#define BM 128
#define BN 128
#define GBK 64
#define KPADH 72
#define A_ST_H (BM * KPADH)
#define STAGE_B (2 * A_ST_H * 2)
#define GEMM_SMEM (2 * STAGE_B)          // 73728 bytes

template<typename OutT>
__global__ void __launch_bounds__(256, 2)
mma_gemm(const __half* __restrict__ A, const __half* __restrict__ Bt,
         OutT* __restrict__ C, int Kp, int NKB, int Ncols)
{
    extern __shared__ __half smh[];
    const uint32_t sbase = smem_u32(smh);
    const int tid  = threadIdx.x;
    const int lane = tid & 31, wid = tid >> 5;
    const int mwarp = wid & 1, nwarp = wid >> 1;
    const int g = lane >> 2, tig = lane & 3;
    const int tile = lane >> 3, lr = lane & 7;
    const int row0 = blockIdx.y * BM, col0 = blockIdx.x * BN;

    float acc[4][4][4];
#pragma unroll
    for (int mi = 0; mi < 4; mi++)
#pragma unroll
        for (int ni = 0; ni < 4; ni++)
#pragma unroll
            for (int r = 0; r < 4; r++) acc[mi][ni][r] = 0.f;

    auto fill = [&](int kb, int s) {
        const uint32_t ab = sbase + (uint32_t)s * STAGE_B;
        const uint32_t bb = ab + A_ST_H * 2;
        const int k0 = kb * GBK;
#pragma unroll
        for (int u = 0; u < 4; u++) {
            int c = tid + u * 256;
            int r = c >> 3, q = c & 7;
            cp16(ab + r * (KPADH * 2) + q * 16,
                 A + (size_t)(row0 + r) * Kp + k0 + q * 8);
            cp16(bb + r * (KPADH * 2) + q * 16,
                 Bt + (size_t)(col0 + r) * Kp + k0 + q * 8);
        }
        cp_commit();
    };

    fill(0, 0);
    if (NKB > 1) fill(1, 1);
    for (int kb = 0; kb < NKB; kb++) {
        if (kb + 1 < NKB) cp_wait<1>(); else cp_wait<0>();
        __syncthreads();

        const uint32_t Ah = sbase + (uint32_t)(kb & 1) * STAGE_B;
        const uint32_t Bh = Ah + A_ST_H * 2;
        const uint32_t a_lane = Ah + (uint32_t)((mwarp * 64 + (tile & 1) * 8 + lr) * KPADH
                                                + (tile >> 1) * 8) * 2;
        const uint32_t b_lane = Bh + (uint32_t)((nwarp * 32 + (tile >> 1) * 8 + lr) * KPADH
                                                + (tile & 1) * 8) * 2;
#pragma unroll
        for (int kk = 0; kk < 4; kk++) {
            uint32_t af[4][4], bf[4][2];
#pragma unroll
            for (int mi = 0; mi < 4; mi++)
                ldm4(af[mi], a_lane + (uint32_t)(mi * 16 * KPADH + kk * 16) * 2);
#pragma unroll
            for (int j = 0; j < 2; j++) {
                uint32_t tmp[4];
                ldm4(tmp, b_lane + (uint32_t)(j * 16 * KPADH + kk * 16) * 2);
                bf[2 * j][0] = tmp[0]; bf[2 * j][1] = tmp[1];
                bf[2 * j + 1][0] = tmp[2]; bf[2 * j + 1][1] = tmp[3];
            }
#pragma unroll
            for (int mi = 0; mi < 4; mi++)
#pragma unroll
                for (int ni = 0; ni < 4; ni++)
                    mma16(acc[mi][ni], af[mi], bf[ni]);
        }
        __syncthreads();
        if (kb + 2 < NKB) fill(kb + 2, kb & 1);
    }

#pragma unroll
    for (int mi = 0; mi < 4; mi++) {
        const int r0 = row0 + mwarp * 64 + mi * 16 + g;
#pragma unroll
        for (int ni = 0; ni < 4; ni++) {
            const int cc = col0 + nwarp * 32 + ni * 8 + 2 * tig;
            if constexpr (sizeof(OutT) == 4) {
                *(float2*)((float*)C + (size_t)r0 * Ncols + cc) =
                    make_float2(acc[mi][ni][0], acc[mi][ni][1]);
                *(float2*)((float*)C + (size_t)(r0 + 8) * Ncols + cc) =
                    make_float2(acc[mi][ni][2], acc[mi][ni][3]);
            } else {
                __half2 h0 = __floats2half2_rn(acc[mi][ni][0], acc[mi][ni][1]);
                __half2 h1 = __floats2half2_rn(acc[mi][ni][2], acc[mi][ni][3]);
                *(__half2*)((__half*)C + (size_t)r0 * Ncols + cc) = h0;
                *(__half2*)((__half*)C + (size_t)(r0 + 8) * Ncols + cc) = h1;
            }
        }
    }
}

// ================= pre/post processing =====================================
__global__ void __launch_bounds__(256)
pack_aug_kernel(const float* __restrict__ x, const float* __restrict__ ev)
{
    long long idx = (long long)blockIdx.x * blockDim.x + threadIdx.x;
    if (idx >= (long long)NTOK * KAUG) return;
    int col = (int)(idx % KAUG);
    long long m = idx / KAUG;
    float v;
    if (col < DMODEL)              v = x[m * DMODEL + col];
    else if (col < DMODEL + EVDIM) v = ev[m * EVDIM + (col - DMODEL)];
    else                           v = 0.f;
    g_augh[idx] = __float2half_rn(v);
}

__global__ void __launch_bounds__(256)
transpose_kernel(const float* __restrict__ src, __half* __restrict__ dst,
                 int K, int N, int Kp)
{
    __shared__ float tile[32][33];
    const int tx = threadIdx.x & 31, ty = threadIdx.x >> 5;
    const int kb = blockIdx.x * 32, nb = blockIdx.y * 32;
#pragma unroll
    for (int u = 0; u < 4; u++) {
        int kk = kb + ty + u * 8;
        tile[ty + u * 8][tx] = (kk < K) ? src[(size_t)kk * N + nb + tx] : 0.f;
    }
    __syncthreads();
#pragma unroll
    for (int u = 0; u < 4; u++) {
        int n = nb + ty + u * 8;
        dst[(size_t)n * Kp + kb + tx] = __float2half_rn(tile[tx][ty + u * 8]);
    }
}

__global__ void __launch_bounds__(256)
conv_silu_kernel(const float* __restrict__ cw, const float* __restrict__ cb)
{
    long long idx = (long long)blockIdx.x * blockDim.x + threadIdx.x;
    if (idx >= (long long)NTOK * DIN) return;
    int ch = (int)(idx & (DIN - 1));
    long long tok = idx >> 11;
    int l = (int)(tok & (SEQLEN - 1));
    long long tok0 = tok - l;
    float acc = cb[ch];
#pragma unroll
    for (int j = 0; j < DCONV; j++) {
        int ls = l - (DCONV - 1) + j;
        if (ls >= 0)
            acc += cw[ch * DCONV + j] *
                   __half2float(g_xzh[(tok0 + ls) * (size_t)(2 * DIN) + ch]);
    }
    g_xch[idx] = __float2half_rn(silu_f(acc));
}

__global__ void __launch_bounds__(256)
dt_post_kernel(const float* __restrict__ dtb, const float* __restrict__ Alog)
{
    int idx = blockIdx.x * blockDim.x + threadIdx.x;
    if (idx >= NTOK * NHEADS) return;
    int h = idx & (NHEADS - 1);
    int tok = idx >> 5;
    float v = __half2float(g_BCh[(size_t)tok * NBC + 2 * DIN + h]) + dtb[h];
    float sp = (v > 20.f) ? v : log1pf(__expf(v));
    g_A[idx] = -__expf(Alog[h]) * sp;
}

// ---------------- fused SSD scan: ONE block per (b,h), 256 threads ---------
// thread t: p = t & 63 (full head dim), ng = t >> 6 owns n-rows ng*16..+16.
__global__ void __launch_bounds__(256)
scan_kernel()
{
    __shared__ __half sBh[2][16][72];
    __shared__ __half sCh[2][16][72];
    __shared__ __half sXh[2][16][72];
    __shared__ float  sAv[2][16];
    __shared__ float  sB[16][68];
    __shared__ float  sC[16][68];
    __shared__ float  sX[16][68];
    __shared__ float  sG[16][16];
    __shared__ float  sCum[16];
    __shared__ float  sPart[16 * 4 * 64];

    const int t = threadIdx.x;
    const int bh = blockIdx.x;
    const int bi = bh >> 5, h = bh & 31;
    const int p  = t & 63;
    const int ng = t >> 6;               // 0..3
    const int i4 = ng * 4;               // finalizes rows i4..i4+3
    const size_t headoff = (size_t)h * HEADDIM;

    const uint32_t uBh = smem_u32(sBh), uCh = smem_u32(sCh);
    const uint32_t uXh = smem_u32(sXh), uAv = smem_u32(sAv);

    auto loadChunk = [&](int c, int st) {
        const size_t l0 = (size_t)bi * SEQLEN + c * BLK;
        {
            // B and C: 128 cp16 each; 256 threads cover both
            int grp = t >> 7;            // 0 = B, 1 = C
            int idx = t & 127;
            int r = idx >> 3, q = idx & 7;
            const size_t rowBC = (l0 + r) * (size_t)NBC + headoff;
            uint32_t so = (uint32_t)(((st * 16 + r) * 72 + q * 8) * 2);
            if (grp == 0) cp16(uBh + so, g_BCh + rowBC + q * 8);
            else          cp16(uCh + so, g_BCh + rowBC + DIN + q * 8);
        }
        if (t < 128) {                   // X: 16 rows x 8 cp16
            int r = t >> 3, q = t & 7;
            uint32_t so = (uint32_t)(((st * 16 + r) * 72 + q * 8) * 2);
            cp16(uXh + so, g_xch + (l0 + r) * (size_t)DIN + headoff + q * 8);
        }
        if (t < 16)
            cp4(uAv + (uint32_t)((st * 16 + t) * 4), g_A + (l0 + t) * NHEADS + h);
        cp_commit();
    };

    float H[16];
#pragma unroll
    for (int i = 0; i < 16; i++) H[i] = 0.f;

    loadChunk(0, 0);
    for (int c = 0; c < NCHUNK; c++) {
        const int st = c & 1;
        if (c + 1 < NCHUNK) { loadChunk(c + 1, st ^ 1); cp_wait<1>(); }
        else                { cp_wait<0>(); }
        __syncthreads();                 // also orders prior H-reads vs converts

        // ---- convert half staging -> f32 (512 half2 each of B, C, X)
#pragma unroll
        for (int u = 0; u < 2; u++) {
            int e = t + u * 256;
            int r = e >> 5, pr = e & 31;
            float2 fb = __half22float2(*(__half2*)&sBh[st][r][pr * 2]);
            float2 fc = __half22float2(*(__half2*)&sCh[st][r][pr * 2]);
            float2 fx = __half22float2(*(__half2*)&sXh[st][r][pr * 2]);
            sB[r][2 * pr] = fb.x; sB[r][2 * pr + 1] = fb.y;
            sC[r][2 * pr] = fc.x; sC[r][2 * pr + 1] = fc.y;
            sX[r][2 * pr] = fx.x; sX[r][2 * pr + 1] = fx.y;
        }
        if (t < 16) {
            float s = 0.f;
            for (int k = 0; k <= t; k++) s += sAv[st][k];
            sCum[t] = s;
        }
        __syncthreads();
        const float cum15 = sCum[15];
        const size_t l0 = (size_t)bi * SEQLEN + c * BLK;

        // ---- G matrix (one entry per thread) + Y_off partials
        {
            int i = t >> 4, j = t & 15;
            float gg = 0.f;
            if (j <= i) {
                float d = 0.f;
#pragma unroll
                for (int n = 0; n < 64; n++) d += sC[i][n] * sB[j][n];
                gg = d * __expf(sCum[i] - sCum[j]);
            }
            sG[i][j] = gg;
        }
        {
            int nb = ng * 16;
#pragma unroll
            for (int i = 0; i < 16; i++) {
                float s = 0.f;
#pragma unroll
                for (int k = 0; k < 16; k++) s += sC[i][nb + k] * H[k];
                sPart[(i * 4 + ng) * 64 + p] = s;
            }
        }
        __syncthreads();

        // ---- Y = Y_diag + exp(cum)*Y_off
        float yv[4];
#pragma unroll
        for (int r = 0; r < 4; r++) {
            int i = i4 + r;
            float s = 0.f;
#pragma unroll
            for (int j = 0; j < 16; j++) s += sG[i][j] * sX[j][p];
            float off = sPart[(i * 4 + 0) * 64 + p] + sPart[(i * 4 + 1) * 64 + p]
                      + sPart[(i * 4 + 2) * 64 + p] + sPart[(i * 4 + 3) * 64 + p];
            yv[r] = s + __expf(sCum[i]) * off;
        }
        __syncthreads();                 // Y_diag reads done before scaling X

        // ---- scale X by decay, write Yz = Y * silu(z)
#pragma unroll
        for (int r = 0; r < 4; r++) {
            int i = i4 + r;
            sX[i][p] *= __expf(cum15 - sCum[i]);
            float zz = __half2float(
                g_xzh[(l0 + i) * (size_t)(2 * DIN) + DIN + headoff + p]);
            g_Yzh[(l0 + i) * (size_t)DIN + headoff + p] =
                __float2half_rn(yv[r] * silu_f(zz));
        }
        __syncthreads();

        // ---- H <- exp(cum15)*H + B^T (decayed X)
        {
            float eA = __expf(cum15);
            int nb = ng * 16;
#pragma unroll
            for (int k = 0; k < 16; k++) {
                float s = 0.f;
#pragma unroll
                for (int i = 0; i < 16; i++) s += sB[i][nb + k] * sX[i][p];
                H[k] = eA * H[k] + s;
            }
        }
    }
}

// ---------------- residual + LayerNorm ----------------
__global__ void __launch_bounds__(256)
ln_kernel(const float* __restrict__ res, const float* __restrict__ gamma,
          const float* __restrict__ beta, float* __restrict__ dout)
{
    const int row = blockIdx.x;
    const int t = threadIdx.x;
    const size_t base = (size_t)row * DMODEL;

    float4 r4 = *(const float4*)(res + base + t * 4);
    float4 o4 = *(const float4*)(g_out + base + t * 4);
    float h0 = r4.x + o4.x, h1 = r4.y + o4.y, h2 = r4.z + o4.z, h3 = r4.w + o4.w;
    float s = h0 + h1 + h2 + h3;
    float sq = h0 * h0 + h1 * h1 + h2 * h2 + h3 * h3;

    __shared__ float red[2][8];
#pragma unroll
    for (int o = 16; o > 0; o >>= 1) {
        s += __shfl_xor_sync(0xffffffffu, s, o);
        sq += __shfl_xor_sync(0xffffffffu, sq, o);
    }
    int wid = t >> 5, lid = t & 31;
    if (lid == 0) { red[0][wid] = s; red[1][wid] = sq; }
    __syncthreads();
    if (t < 32) {
        s = (t < 8) ? red[0][t] : 0.f;
        sq = (t < 8) ? red[1][t] : 0.f;
#pragma unroll
        for (int o = 4; o > 0; o >>= 1) {
            s += __shfl_xor_sync(0xffffffffu, s, o);
            sq += __shfl_xor_sync(0xffffffffu, sq, o);
        }
        if (t == 0) { red[0][0] = s; red[1][0] = sq; }
    }
    __syncthreads();
    float mu = red[0][0] * (1.f / DMODEL);
    float var = red[1][0] * (1.f / DMODEL) - mu * mu;
    float inv = rsqrtf(var + 1e-5f);

    float4 g4 = *(const float4*)(gamma + t * 4);
    float4 b4 = *(const float4*)(beta + t * 4);
    float4 ov;
    ov.x = (h0 - mu) * inv * g4.x + b4.x;
    ov.y = (h1 - mu) * inv * g4.y + b4.y;
    ov.z = (h2 - mu) * inv * g4.z + b4.z;
    ov.w = (h3 - mu) * inv * g4.w + b4.w;
    *(float4*)(dout + base + t * 4) = ov;
}

// ---------------- launcher ----------------
extern "C" void kernel_launch(void* const* d_in, const int* in_sizes, int n_in,
                              void* d_out, int out_size)
{
    const float* x        = (const float*)d_in[0];
    const float* ev       = (const float*)d_in[1];
    const float* w_in     = (const float*)d_in[2];   // (1040,4096)
    const float* conv_w   = (const float*)d_in[3];
    const float* conv_b   = (const float*)d_in[4];
    const float* A_log    = (const float*)d_in[5];
    const float* w_B      = (const float*)d_in[6];   // (2048,2048)
    const float* w_C      = (const float*)d_in[7];
    const float* w_dt     = (const float*)d_in[8];   // (2048,32)
    const float* b_dt     = (const float*)d_in[9];
    const float* w_out    = (const float*)d_in[10];  // (2048,1024)
    const float* ln_gamma = (const float*)d_in[11];
    const float* ln_beta  = (const float*)d_in[12];
    float* out = (float*)d_out;

    cudaFuncSetAttribute(mma_gemm<__half>, cudaFuncAttributeMaxDynamicSharedMemorySize,
                         GEMM_SMEM);
    cudaFuncSetAttribute(mma_gemm<float>, cudaFuncAttributeMaxDynamicSharedMemorySize,
                         GEMM_SMEM);

    __half *p_augh, *p_winth, *p_wbcth, *p_woth, *p_xch, *p_Yzh, *p_xzh, *p_BCh;
    float *p_outb;
    cudaGetSymbolAddress((void**)&p_augh,  g_augh);
    cudaGetSymbolAddress((void**)&p_winth, g_winth);
    cudaGetSymbolAddress((void**)&p_wbcth, g_wbcth);
    cudaGetSymbolAddress((void**)&p_woth,  g_woth);
    cudaGetSymbolAddress((void**)&p_xch,   g_xch);
    cudaGetSymbolAddress((void**)&p_Yzh,   g_Yzh);
    cudaGetSymbolAddress((void**)&p_xzh,   g_xzh);
    cudaGetSymbolAddress((void**)&p_BCh,   g_BCh);
    cudaGetSymbolAddress((void**)&p_outb,  g_out);

    // 0) pack + weight transposes (f32 -> half)
    {
        long long n = (long long)NTOK * KAUG;
        pack_aug_kernel<<<(unsigned)((n + 255) / 256), 256>>>(x, ev);
    }
    transpose_kernel<<<dim3(KAUG / 32, 4096 / 32), 256>>>(w_in, p_winth, 1040, 4096, KAUG);
    transpose_kernel<<<dim3(DIN / 32, DIN / 32), 256>>>(w_B, p_wbcth, DIN, DIN, DIN);
    transpose_kernel<<<dim3(DIN / 32, DIN / 32), 256>>>(w_C, p_wbcth + (size_t)DIN * DIN,
                                                        DIN, DIN, DIN);
    transpose_kernel<<<dim3(DIN / 32, 1), 256>>>(w_dt, p_wbcth + (size_t)2 * DIN * DIN,
                                                 DIN, 32, DIN);
    transpose_kernel<<<dim3(DIN / 32, DMODEL / 32), 256>>>(w_out, p_woth, DIN, DMODEL, DIN);

    // 1) xz = aug @ w_in            (16384 x 4096, K=1088) -> half
    mma_gemm<__half><<<dim3(4096 / BN, NTOK / BM), 256, GEMM_SMEM>>>(
        p_augh, p_winth, p_xzh, KAUG, KAUG / GBK, 4096);
    // 2) xc = silu(conv(x_path)+b) -> half
    {
        long long n = (long long)NTOK * DIN;
        conv_silu_kernel<<<(unsigned)((n + 255) / 256), 256>>>(conv_w, conv_b);
    }
    // 3) [B|C|dt] = xc @ [w_B|w_C|w_dt]  (16384 x 4224, K=2048) -> half
    mma_gemm<__half><<<dim3(NBC / BN, NTOK / BM), 256, GEMM_SMEM>>>(
        p_xch, p_wbcth, p_BCh, DIN, DIN / GBK, NBC);
    // 4) A from dtraw
    dt_post_kernel<<<(NTOK * NHEADS) / 256, 256>>>(b_dt, A_log);
    // 5) scan -> Yz (half)   (one block per (b,h), full head dim)
    scan_kernel<<<BATCH * NHEADS, 256>>>();
    // 6) out = Yz @ w_out           (16384 x 1024, K=2048) -> f32
    mma_gemm<float><<<dim3(DMODEL / BN, NTOK / BM), 256, GEMM_SMEM>>>(
        p_Yzh, p_woth, p_outb, DIN, DIN / GBK, DMODEL);
    // 7) LayerNorm(residual + out)
    ln_kernel<<<NTOK, 256>>>(x, ln_gamma, ln_beta, out);
}

// round 12
// speedup vs baseline: 1.0143x; 1.0143x over previous
#include <cuda_runtime.h>
#include <cuda_fp16.h>
#include <cstdint>

// ---------------- problem constants ----------------
#define BATCH     4
#define SEQLEN    4096
#define NTOK      (BATCH * SEQLEN)      // 16384
#define DMODEL    1024
#define EVDIM     16
#define DIN       2048                  // d_inner
#define NHEADS    32
#define DSTATE    64
#define HEADDIM   64
#define DCONV     4
#define BLK       16                    // block_len
#define NCHUNK    (SEQLEN / BLK)        // 256
#define KAUG      1088                  // 1040 padded to multiple of 64
#define NBC       4224                  // 2048 B + 2048 C + 32 dt + 96 pad

// ---------------- scratch (device globals; no runtime allocation) ----------
__device__ __half g_augh [ (size_t)NTOK * KAUG ];    // [x | ev | 0pad] (half)
__device__ __half g_winth[ (size_t)4096 * KAUG ];    // in_proj_w^T (half)
__device__ __half g_wbcth[ (size_t)NBC * DIN ];      // [w_B^T ; w_C^T ; w_dt^T ; 0]
__device__ __half g_woth [ (size_t)DMODEL * DIN ];   // out_proj_w^T (half)
__device__ __half g_xzh  [ (size_t)NTOK * 2 * DIN ]; // x_path | z (half)
__device__ __half g_xch  [ (size_t)NTOK * DIN ];     // conv+silu out (half)
__device__ __half g_BCh  [ (size_t)NTOK * NBC ];     // [B | C | dtraw | pad] (half)
__device__ __half g_Yzh  [ (size_t)NTOK * DIN ];     // Y*silu(z) (half)
__device__ __half g_outh [ (size_t)NTOK * DMODEL ];  // pre-LN (half)
__device__ float  g_A    [ (size_t)NTOK * NHEADS ];

// ================= helpers =================================================
__device__ __forceinline__ uint32_t smem_u32(const void* p) {
    uint32_t a;
    asm("{ .reg .u64 t; cvta.to.shared.u64 t, %1; cvt.u32.u64 %0, t; }"
        : "=r"(a) : "l"(p));
    return a;
}
__device__ __forceinline__ void cp16(uint32_t s, const void* g) {
    asm volatile("cp.async.cg.shared.global [%0], [%1], 16;\n" :: "r"(s), "l"(g));
}
__device__ __forceinline__ void cp4(uint32_t s, const void* g) {
    asm volatile("cp.async.ca.shared.global [%0], [%1], 4;\n" :: "r"(s), "l"(g));
}
__device__ __forceinline__ void cp_commit() { asm volatile("cp.async.commit_group;\n" ::); }
template<int N> __device__ __forceinline__ void cp_wait() {
    asm volatile("cp.async.wait_group %0;\n" :: "n"(N));
}
__device__ __forceinline__ void ldm4(uint32_t* r, uint32_t addr) {
    asm volatile("ldmatrix.sync.aligned.m8n8.x4.shared.b16 {%0,%1,%2,%3}, [%4];"
        : "=r"(r[0]), "=r"(r[1]), "=r"(r[2]), "=r"(r[3]) : "r"(addr));
}
__device__ __forceinline__ void mma16(float* c, const uint32_t* a, const uint32_t* b) {
    asm volatile(
        "mma.sync.aligned.m16n8k16.row.col.f32.f16.f16.f32 "
        "{%0,%1,%2,%3}, {%4,%5,%6,%7}, {%8,%9}, {%0,%1,%2,%3};"
        : "+f"(c[0]), "+f"(c[1]), "+f"(c[2]), "+f"(c[3])
        : "r"(a[0]), "r"(a[1]), "r"(a[2]), "r"(a[3]), "r"(b[0]), "r"(b[1]));
}
__device__ __forceinline__ float silu_f(float z) { return z / (1.f + __expf(-z)); }

// ================= fp16 warp-MMA GEMM (R9 proven: 2-stage, 2 CTAs/SM) ======
#define BM 128
#define BN 128
#define GBK 64
#define KPADH 72
#define A_ST_H (BM * KPADH)
#define STAGE_B (2 * A_ST_H * 2)
#define GEMM_SMEM (2 * STAGE_B)          // 73728 bytes

template<typename OutT>
__global__ void __launch_bounds__(256, 2)
mma_gemm(const __half* __restrict__ A, const __half* __restrict__ Bt,
         OutT* __restrict__ C, int Kp, int NKB, int Ncols)
{
    extern __shared__ __half smh[];
    const uint32_t sbase = smem_u32(smh);
    const int tid  = threadIdx.x;
    const int lane = tid & 31, wid = tid >> 5;
    const int mwarp = wid & 1, nwarp = wid >> 1;
    const int g = lane >> 2, tig = lane & 3;
    const int tile = lane >> 3, lr = lane & 7;
    const int row0 = blockIdx.y * BM, col0 = blockIdx.x * BN;

    float acc[4][4][4];
#pragma unroll
    for (int mi = 0; mi < 4; mi++)
#pragma unroll
        for (int ni = 0; ni < 4; ni++)
#pragma unroll
            for (int r = 0; r < 4; r++) acc[mi][ni][r] = 0.f;

    auto fill = [&](int kb, int s) {
        const uint32_t ab = sbase + (uint32_t)s * STAGE_B;
        const uint32_t bb = ab + A_ST_H * 2;
        const int k0 = kb * GBK;
#pragma unroll
        for (int u = 0; u < 4; u++) {
            int c = tid + u * 256;
            int r = c >> 3, q = c & 7;
            cp16(ab + r * (KPADH * 2) + q * 16,
                 A + (size_t)(row0 + r) * Kp + k0 + q * 8);
            cp16(bb + r * (KPADH * 2) + q * 16,
                 Bt + (size_t)(col0 + r) * Kp + k0 + q * 8);
        }
        cp_commit();
    };

    fill(0, 0);
    if (NKB > 1) fill(1, 1);
    for (int kb = 0; kb < NKB; kb++) {
        if (kb + 1 < NKB) cp_wait<1>(); else cp_wait<0>();
        __syncthreads();

        const uint32_t Ah = sbase + (uint32_t)(kb & 1) * STAGE_B;
        const uint32_t Bh = Ah + A_ST_H * 2;
        const uint32_t a_lane = Ah + (uint32_t)((mwarp * 64 + (tile & 1) * 8 + lr) * KPADH
                                                + (tile >> 1) * 8) * 2;
        const uint32_t b_lane = Bh + (uint32_t)((nwarp * 32 + (tile >> 1) * 8 + lr) * KPADH
                                                + (tile & 1) * 8) * 2;
#pragma unroll
        for (int kk = 0; kk < 4; kk++) {
            uint32_t af[4][4], bf[4][2];
#pragma unroll
            for (int mi = 0; mi < 4; mi++)
                ldm4(af[mi], a_lane + (uint32_t)(mi * 16 * KPADH + kk * 16) * 2);
#pragma unroll
            for (int j = 0; j < 2; j++) {
                uint32_t tmp[4];
                ldm4(tmp, b_lane + (uint32_t)(j * 16 * KPADH + kk * 16) * 2);
                bf[2 * j][0] = tmp[0]; bf[2 * j][1] = tmp[1];
                bf[2 * j + 1][0] = tmp[2]; bf[2 * j + 1][1] = tmp[3];
            }
#pragma unroll
            for (int mi = 0; mi < 4; mi++)
#pragma unroll
                for (int ni = 0; ni < 4; ni++)
                    mma16(acc[mi][ni], af[mi], bf[ni]);
        }
        __syncthreads();
        if (kb + 2 < NKB) fill(kb + 2, kb & 1);
    }

#pragma unroll
    for (int mi = 0; mi < 4; mi++) {
        const int r0 = row0 + mwarp * 64 + mi * 16 + g;
#pragma unroll
        for (int ni = 0; ni < 4; ni++) {
            const int cc = col0 + nwarp * 32 + ni * 8 + 2 * tig;
            if constexpr (sizeof(OutT) == 4) {
                *(float2*)((float*)C + (size_t)r0 * Ncols + cc) =
                    make_float2(acc[mi][ni][0], acc[mi][ni][1]);
                *(float2*)((float*)C + (size_t)(r0 + 8) * Ncols + cc) =
                    make_float2(acc[mi][ni][2], acc[mi][ni][3]);
            } else {
                __half2 h0 = __floats2half2_rn(acc[mi][ni][0], acc[mi][ni][1]);
                __half2 h1 = __floats2half2_rn(acc[mi][ni][2], acc[mi][ni][3]);
                *(__half2*)((__half*)C + (size_t)r0 * Ncols + cc) = h0;
                *(__half2*)((__half*)C + (size_t)(r0 + 8) * Ncols + cc) = h1;
            }
        }
    }
}

// ================= pre/post processing =====================================
__global__ void __launch_bounds__(256)
pack_aug_kernel(const float* __restrict__ x, const float* __restrict__ ev)
{
    long long idx = (long long)blockIdx.x * blockDim.x + threadIdx.x;
    if (idx >= (long long)NTOK * KAUG) return;
    int col = (int)(idx % KAUG);
    long long m = idx / KAUG;
    float v;
    if (col < DMODEL)              v = x[m * DMODEL + col];
    else if (col < DMODEL + EVDIM) v = ev[m * EVDIM + (col - DMODEL)];
    else                           v = 0.f;
    g_augh[idx] = __float2half_rn(v);
}

__global__ void __launch_bounds__(256)
transpose_kernel(const float* __restrict__ src, __half* __restrict__ dst,
                 int K, int N, int Kp)
{
    __shared__ float tile[32][33];
    const int tx = threadIdx.x & 31, ty = threadIdx.x >> 5;
    const int kb = blockIdx.x * 32, nb = blockIdx.y * 32;
#pragma unroll
    for (int u = 0; u < 4; u++) {
        int kk = kb + ty + u * 8;
        tile[ty + u * 8][tx] = (kk < K) ? src[(size_t)kk * N + nb + tx] : 0.f;
    }
    __syncthreads();
#pragma unroll
    for (int u = 0; u < 4; u++) {
        int n = nb + ty + u * 8;
        dst[(size_t)n * Kp + kb + tx] = __float2half_rn(tile[tx][ty + u * 8]);
    }
}

__global__ void __launch_bounds__(256)
conv_silu_kernel(const float* __restrict__ cw, const float* __restrict__ cb)
{
    long long idx = (long long)blockIdx.x * blockDim.x + threadIdx.x;
    if (idx >= (long long)NTOK * DIN) return;
    int ch = (int)(idx & (DIN - 1));
    long long tok = idx >> 11;
    int l = (int)(tok & (SEQLEN - 1));
    long long tok0 = tok - l;
    float acc = cb[ch];
#pragma unroll
    for (int j = 0; j < DCONV; j++) {
        int ls = l - (DCONV - 1) + j;
        if (ls >= 0)
            acc += cw[ch * DCONV + j] *
                   __half2float(g_xzh[(tok0 + ls) * (size_t)(2 * DIN) + ch]);
    }
    g_xch[idx] = __float2half_rn(silu_f(acc));
}

__global__ void __launch_bounds__(256)
dt_post_kernel(const float* __restrict__ dtb, const float* __restrict__ Alog)
{
    int idx = blockIdx.x * blockDim.x + threadIdx.x;
    if (idx >= NTOK * NHEADS) return;
    int h = idx & (NHEADS - 1);
    int tok = idx >> 5;
    float v = __half2float(g_BCh[(size_t)tok * NBC + 2 * DIN + h]) + dtb[h];
    float sp = (v > 20.f) ? v : log1pf(__expf(v));
    g_A[idx] = -__expf(Alog[h]) * sp;
}

// ---------------- fused SSD scan (R9-proven: split p, half staging) --------
__global__ void __launch_bounds__(128)
scan_kernel()
{
    __shared__ __half sBh[2][16][72];
    __shared__ __half sCh[2][16][72];
    __shared__ __half sXh[2][16][40];
    __shared__ float  sAv[2][16];
    __shared__ float  sB[16][68];
    __shared__ float  sC[16][68];
    __shared__ float  sX[16][36];
    __shared__ float  sG[16][16];
    __shared__ float  sCum[16];
    __shared__ float  sPart[16 * 4 * 32];

    const int t = threadIdx.x;
    const int bh = blockIdx.x;
    const int bi = bh >> 5, h = bh & 31;
    const int p0 = blockIdx.y * 32;
    const int p = t & 31;
    const int ng = t >> 5;
    const int i4 = ng * 4;
    const size_t headoff = (size_t)h * HEADDIM;

    const uint32_t uBh = smem_u32(sBh), uCh = smem_u32(sCh);
    const uint32_t uXh = smem_u32(sXh), uAv = smem_u32(sAv);

    auto loadChunk = [&](int c, int st) {
        const size_t l0 = (size_t)bi * SEQLEN + c * BLK;
        {
            int r = t >> 3, q = t & 7;
            const size_t rowBC = (l0 + r) * (size_t)NBC + headoff;
            uint32_t so = (uint32_t)(((st * 16 + r) * 72 + q * 8) * 2);
            cp16(uBh + so, g_BCh + rowBC + q * 8);
            cp16(uCh + so, g_BCh + rowBC + DIN + q * 8);
        }
        if (t < 64) {
            int r = t >> 2, q = t & 3;
            uint32_t so = (uint32_t)(((st * 16 + r) * 40 + q * 8) * 2);
            cp16(uXh + so, g_xch + (l0 + r) * (size_t)DIN + headoff + p0 + q * 8);
        }
        if (t < 16)
            cp4(uAv + (uint32_t)((st * 16 + t) * 4), g_A + (l0 + t) * NHEADS + h);
        cp_commit();
    };

    float H[16];
#pragma unroll
    for (int i = 0; i < 16; i++) H[i] = 0.f;

    loadChunk(0, 0);
    for (int c = 0; c < NCHUNK; c++) {
        const int st = c & 1;
        if (c + 1 < NCHUNK) { loadChunk(c + 1, st ^ 1); cp_wait<1>(); }
        else                { cp_wait<0>(); }
        __syncthreads();

#pragma unroll
        for (int u = 0; u < 4; u++) {
            int e = t + u * 128;
            int r = e >> 5, pr = e & 31;
            float2 fb = __half22float2(*(__half2*)&sBh[st][r][pr * 2]);
            float2 fc = __half22float2(*(__half2*)&sCh[st][r][pr * 2]);
            sB[r][2 * pr] = fb.x; sB[r][2 * pr + 1] = fb.y;
            sC[r][2 * pr] = fc.x; sC[r][2 * pr + 1] = fc.y;
        }
#pragma unroll
        for (int u = 0; u < 2; u++) {
            int e = t + u * 128;
            int r = e >> 4, pr = e & 15;
            float2 fx = __half22float2(*(__half2*)&sXh[st][r][pr * 2]);
            sX[r][2 * pr] = fx.x; sX[r][2 * pr + 1] = fx.y;
        }
        if (t < 16) {
            float s = 0.f;
            for (int k = 0; k <= t; k++) s += sAv[st][k];
            sCum[t] = s;
        }
        __syncthreads();
        const float cum15 = sCum[15];
        const size_t l0 = (size_t)bi * SEQLEN + c * BLK;

#pragma unroll
        for (int u = 0; u < 2; u++) {
            int e = t + u * 128;
            int i = e >> 4, j = e & 15;
            float gg = 0.f;
            if (j <= i) {
                float d = 0.f;
#pragma unroll
                for (int n = 0; n < 64; n++) d += sC[i][n] * sB[j][n];
                gg = d * __expf(sCum[i] - sCum[j]);
            }
            sG[i][j] = gg;
        }
        {
            int nb = ng * 16;
#pragma unroll
            for (int i = 0; i < 16; i++) {
                float s = 0.f;
#pragma unroll
                for (int k = 0; k < 16; k++) s += sC[i][nb + k] * H[k];
                sPart[(i * 4 + ng) * 32 + p] = s;
            }
        }
        __syncthreads();

        float yv[4];
#pragma unroll
        for (int r = 0; r < 4; r++) {
            int i = i4 + r;
            float s = 0.f;
#pragma unroll
            for (int j = 0; j < 16; j++) s += sG[i][j] * sX[j][p];
            float off = sPart[(i * 4 + 0) * 32 + p] + sPart[(i * 4 + 1) * 32 + p]
                      + sPart[(i * 4 + 2) * 32 + p] + sPart[(i * 4 + 3) * 32 + p];
            yv[r] = s + __expf(sCum[i]) * off;
        }
        __syncthreads();

#pragma unroll
        for (int r = 0; r < 4; r++) {
            int i = i4 + r;
            sX[i][p] *= __expf(cum15 - sCum[i]);
            float zz = __half2float(
                g_xzh[(l0 + i) * (size_t)(2 * DIN) + DIN + headoff + p0 + p]);
            g_Yzh[(l0 + i) * (size_t)DIN + headoff + p0 + p] =
                __float2half_rn(yv[r] * silu_f(zz));
        }
        __syncthreads();

        {
            float eA = __expf(cum15);
            int nb = ng * 16;
#pragma unroll
            for (int k = 0; k < 16; k++) {
                float s = 0.f;
#pragma unroll
                for (int i = 0; i < 16; i++) s += sB[i][nb + k] * sX[i][p];
                H[k] = eA * H[k] + s;
            }
        }
    }
}

// ---------------- residual + LayerNorm (reads half pre-LN) ----------------
__global__ void __launch_bounds__(256)
ln_kernel(const float* __restrict__ res, const float* __restrict__ gamma,
          const float* __restrict__ beta, float* __restrict__ dout)
{
    const int row = blockIdx.x;
    const int t = threadIdx.x;
    const size_t base = (size_t)row * DMODEL;

    float4 r4 = *(const float4*)(res + base + t * 4);
    __half2 oh0 = *(const __half2*)(g_outh + base + t * 4);
    __half2 oh1 = *(const __half2*)(g_outh + base + t * 4 + 2);
    float2 of0 = __half22float2(oh0), of1 = __half22float2(oh1);
    float h0 = r4.x + of0.x, h1 = r4.y + of0.y, h2 = r4.z + of1.x, h3 = r4.w + of1.y;
    float s = h0 + h1 + h2 + h3;
    float sq = h0 * h0 + h1 * h1 + h2 * h2 + h3 * h3;

    __shared__ float red[2][8];
#pragma unroll
    for (int o = 16; o > 0; o >>= 1) {
        s += __shfl_xor_sync(0xffffffffu, s, o);
        sq += __shfl_xor_sync(0xffffffffu, sq, o);
    }
    int wid = t >> 5, lid = t & 31;
    if (lid == 0) { red[0][wid] = s; red[1][wid] = sq; }
    __syncthreads();
    if (t < 32) {
        s = (t < 8) ? red[0][t] : 0.f;
        sq = (t < 8) ? red[1][t] : 0.f;
#pragma unroll
        for (int o = 4; o > 0; o >>= 1) {
            s += __shfl_xor_sync(0xffffffffu, s, o);
            sq += __shfl_xor_sync(0xffffffffu, sq, o);
        }
        if (t == 0) { red[0][0] = s; red[1][0] = sq; }
    }
    __syncthreads();
    float mu = red[0][0] * (1.f / DMODEL);
    float var = red[1][0] * (1.f / DMODEL) - mu * mu;
    float inv = rsqrtf(var + 1e-5f);

    float4 g4 = *(const float4*)(gamma + t * 4);
    float4 b4 = *(const float4*)(beta + t * 4);
    float4 ov;
    ov.x = (h0 - mu) * inv * g4.x + b4.x;
    ov.y = (h1 - mu) * inv * g4.y + b4.y;
    ov.z = (h2 - mu) * inv * g4.z + b4.z;
    ov.w = (h3 - mu) * inv * g4.w + b4.w;
    *(float4*)(dout + base + t * 4) = ov;
}

// ---------------- launcher ----------------
extern "C" void kernel_launch(void* const* d_in, const int* in_sizes, int n_in,
                              void* d_out, int out_size)
{
    const float* x        = (const float*)d_in[0];
    const float* ev       = (const float*)d_in[1];
    const float* w_in     = (const float*)d_in[2];   // (1040,4096)
    const float* conv_w   = (const float*)d_in[3];
    const float* conv_b   = (const float*)d_in[4];
    const float* A_log    = (const float*)d_in[5];
    const float* w_B      = (const float*)d_in[6];   // (2048,2048)
    const float* w_C      = (const float*)d_in[7];
    const float* w_dt     = (const float*)d_in[8];   // (2048,32)
    const float* b_dt     = (const float*)d_in[9];
    const float* w_out    = (const float*)d_in[10];  // (2048,1024)
    const float* ln_gamma = (const float*)d_in[11];
    const float* ln_beta  = (const float*)d_in[12];
    float* out = (float*)d_out;

    cudaFuncSetAttribute(mma_gemm<__half>, cudaFuncAttributeMaxDynamicSharedMemorySize,
                         GEMM_SMEM);

    __half *p_augh, *p_winth, *p_wbcth, *p_woth, *p_xch, *p_Yzh, *p_xzh, *p_BCh, *p_outh;
    cudaGetSymbolAddress((void**)&p_augh,  g_augh);
    cudaGetSymbolAddress((void**)&p_winth, g_winth);
    cudaGetSymbolAddress((void**)&p_wbcth, g_wbcth);
    cudaGetSymbolAddress((void**)&p_woth,  g_woth);
    cudaGetSymbolAddress((void**)&p_xch,   g_xch);
    cudaGetSymbolAddress((void**)&p_Yzh,   g_Yzh);
    cudaGetSymbolAddress((void**)&p_xzh,   g_xzh);
    cudaGetSymbolAddress((void**)&p_BCh,   g_BCh);
    cudaGetSymbolAddress((void**)&p_outh,  g_outh);

    // launches 0-4: pack + 4 transposes (w_out transpose moved later so that
    // launch index 5 = GEMM1, which is what ncu (-s 5 -c 1) profiles)
    {
        long long n = (long long)NTOK * KAUG;
        pack_aug_kernel<<<(unsigned)((n + 255) / 256), 256>>>(x, ev);                 // 0
    }
    transpose_kernel<<<dim3(KAUG / 32, 4096 / 32), 256>>>(w_in, p_winth, 1040, 4096, KAUG); // 1
    transpose_kernel<<<dim3(DIN / 32, DIN / 32), 256>>>(w_B, p_wbcth, DIN, DIN, DIN);       // 2
    transpose_kernel<<<dim3(DIN / 32, DIN / 32), 256>>>(w_C, p_wbcth + (size_t)DIN * DIN,
                                                        DIN, DIN, DIN);                     // 3
    transpose_kernel<<<dim3(DIN / 32, 1), 256>>>(w_dt, p_wbcth + (size_t)2 * DIN * DIN,
                                                 DIN, 32, DIN);                             // 4

    // 5) xz = aug @ w_in            (16384 x 4096, K=1088) -> half  [PROFILED]
    mma_gemm<__half><<<dim3(4096 / BN, NTOK / BM), 256, GEMM_SMEM>>>(
        p_augh, p_winth, p_xzh, KAUG, KAUG / GBK, 4096);

    // w_out transpose (only needed before GEMM3)
    transpose_kernel<<<dim3(DIN / 32, DMODEL / 32), 256>>>(w_out, p_woth, DIN, DMODEL, DIN);

    // xc = silu(conv(x_path)+b) -> half
    {
        long long n = (long long)NTOK * DIN;
        conv_silu_kernel<<<(unsigned)((n + 255) / 256), 256>>>(conv_w, conv_b);
    }
    // [B|C|dt] = xc @ [w_B|w_C|w_dt]  (16384 x 4224, K=2048) -> half
    mma_gemm<__half><<<dim3(NBC / BN, NTOK / BM), 256, GEMM_SMEM>>>(
        p_xch, p_wbcth, p_BCh, DIN, DIN / GBK, NBC);
    // A from dtraw
    dt_post_kernel<<<(NTOK * NHEADS) / 256, 256>>>(b_dt, A_log);
    // scan -> Yz (half)
    scan_kernel<<<dim3(BATCH * NHEADS, 2), 128>>>();
    // out = Yz @ w_out              (16384 x 1024, K=2048) -> half
    mma_gemm<__half><<<dim3(DMODEL / BN, NTOK / BM), 256, GEMM_SMEM>>>(
        p_Yzh, p_woth, p_outh, DIN, DIN / GBK, DMODEL);
    // LayerNorm(residual + out)
    ln_kernel<<<NTOK, 256>>>(x, ln_gamma, ln_beta, out);
}

// round 14
// speedup vs baseline: 1.0171x; 1.0028x over previous
#include <cuda_runtime.h>
#include <cuda_fp16.h>
#include <cstdint>

// ---------------- problem constants ----------------
#define BATCH     4
#define SEQLEN    4096
#define NTOK      (BATCH * SEQLEN)      // 16384
#define DMODEL    1024
#define EVDIM     16
#define DIN       2048                  // d_inner
#define NHEADS    32
#define DSTATE    64
#define HEADDIM   64
#define DCONV     4
#define BLK       16                    // block_len
#define NCHUNK    (SEQLEN / BLK)        // 256
#define KAUG      1088                  // 1040 padded to multiple of 64
#define NBC       4224                  // 2048 B + 2048 C + 32 dt + 96 pad

// ---------------- scratch (device globals; no runtime allocation) ----------
__device__ __half g_augh [ (size_t)NTOK * KAUG ];    // [x | ev | 0pad] (half)
__device__ __half g_winth[ (size_t)4096 * KAUG ];    // in_proj_w^T (half)
__device__ __half g_wbcth[ (size_t)NBC * DIN ];      // [w_B^T ; w_C^T ; w_dt^T ; 0]
__device__ __half g_woth [ (size_t)DMODEL * DIN ];   // out_proj_w^T (half)
__device__ __half g_xzh  [ (size_t)NTOK * 2 * DIN ]; // x_path | z (half)
__device__ __half g_xch  [ (size_t)NTOK * DIN ];     // conv+silu out (half)
__device__ __half g_BCh  [ (size_t)NTOK * NBC ];     // [B | C | dtraw | pad] (half)
__device__ __half g_Yzh  [ (size_t)NTOK * DIN ];     // Y*silu(z) (half)
__device__ __half g_outh [ (size_t)NTOK * DMODEL ];  // pre-LN (half)
__device__ float  g_A    [ (size_t)NTOK * NHEADS ];

// ================= helpers =================================================
__device__ __forceinline__ uint32_t smem_u32(const void* p) {
    uint32_t a;
    asm("{ .reg .u64 t; cvta.to.shared.u64 t, %1; cvt.u32.u64 %0, t; }"
        : "=r"(a) : "l"(p));
    return a;
}
__device__ __forceinline__ void cp16(uint32_t s, const void* g) {
    asm volatile("cp.async.cg.shared.global [%0], [%1], 16;\n" :: "r"(s), "l"(g));
}
__device__ __forceinline__ void cp4(uint32_t s, const void* g) {
    asm volatile("cp.async.ca.shared.global [%0], [%1], 4;\n" :: "r"(s), "l"(g));
}
__device__ __forceinline__ void cp_commit() { asm volatile("cp.async.commit_group;\n" ::); }
template<int N> __device__ __forceinline__ void cp_wait() {
    asm volatile("cp.async.wait_group %0;\n" :: "n"(N));
}
__device__ __forceinline__ void ldm4(uint32_t* r, uint32_t addr) {
    asm volatile("ldmatrix.sync.aligned.m8n8.x4.shared.b16 {%0,%1,%2,%3}, [%4];"
        : "=r"(r[0]), "=r"(r[1]), "=r"(r[2]), "=r"(r[3]) : "r"(addr));
}
__device__ __forceinline__ void mma16(float* c, const uint32_t* a, const uint32_t* b) {
    asm volatile(
        "mma.sync.aligned.m16n8k16.row.col.f32.f16.f16.f32 "
        "{%0,%1,%2,%3}, {%4,%5,%6,%7}, {%8,%9}, {%0,%1,%2,%3};"
        : "+f"(c[0]), "+f"(c[1]), "+f"(c[2]), "+f"(c[3])
        : "r"(a[0]), "r"(a[1]), "r"(a[2]), "r"(a[3]), "r"(b[0]), "r"(b[1]));
}
__device__ __forceinline__ float silu_f(float z) { return z / (1.f + __expf(-z)); }

// ================= fp16 warp-MMA GEMM (R9 proven: 2-stage, 2 CTAs/SM) ======
#define BM 128
#define BN 128
#define GBK 64
#define KPADH 72
#define A_ST_H (BM * KPADH)
#define STAGE_B (2 * A_ST_H * 2)
#define GEMM_SMEM (2 * STAGE_B)          // 73728 bytes

template<typename OutT>
__global__ void __launch_bounds__(256, 2)
mma_gemm(const __half* __restrict__ A, const __half* __restrict__ Bt,
         OutT* __restrict__ C, int Kp, int NKB, int Ncols, int col_base)
{
    extern __shared__ __half smh[];
    const uint32_t sbase = smem_u32(smh);
    const int tid  = threadIdx.x;
    const int lane = tid & 31, wid = tid >> 5;
    const int mwarp = wid & 1, nwarp = wid >> 1;
    const int g = lane >> 2, tig = lane & 3;
    const int tile = lane >> 3, lr = lane & 7;
    const int row0 = blockIdx.y * BM, col0 = blockIdx.x * BN + col_base;

    float acc[4][4][4];
#pragma unroll
    for (int mi = 0; mi < 4; mi++)
#pragma unroll
        for (int ni = 0; ni < 4; ni++)
#pragma unroll
            for (int r = 0; r < 4; r++) acc[mi][ni][r] = 0.f;

    auto fill = [&](int kb, int s) {
        const uint32_t ab = sbase + (uint32_t)s * STAGE_B;
        const uint32_t bb = ab + A_ST_H * 2;
        const int k0 = kb * GBK;
#pragma unroll
        for (int u = 0; u < 4; u++) {
            int c = tid + u * 256;
            int r = c >> 3, q = c & 7;
            cp16(ab + r * (KPADH * 2) + q * 16,
                 A + (size_t)(row0 + r) * Kp + k0 + q * 8);
            cp16(bb + r * (KPADH * 2) + q * 16,
                 Bt + (size_t)(col0 + r) * Kp + k0 + q * 8);
        }
        cp_commit();
    };

    fill(0, 0);
    if (NKB > 1) fill(1, 1);
    for (int kb = 0; kb < NKB; kb++) {
        if (kb + 1 < NKB) cp_wait<1>(); else cp_wait<0>();
        __syncthreads();

        const uint32_t Ah = sbase + (uint32_t)(kb & 1) * STAGE_B;
        const uint32_t Bh = Ah + A_ST_H * 2;
        const uint32_t a_lane = Ah + (uint32_t)((mwarp * 64 + (tile & 1) * 8 + lr) * KPADH
                                                + (tile >> 1) * 8) * 2;
        const uint32_t b_lane = Bh + (uint32_t)((nwarp * 32 + (tile >> 1) * 8 + lr) * KPADH
                                                + (tile & 1) * 8) * 2;
#pragma unroll
        for (int kk = 0; kk < 4; kk++) {
            uint32_t af[4][4], bf[4][2];
#pragma unroll
            for (int mi = 0; mi < 4; mi++)
                ldm4(af[mi], a_lane + (uint32_t)(mi * 16 * KPADH + kk * 16) * 2);
#pragma unroll
            for (int j = 0; j < 2; j++) {
                uint32_t tmp[4];
                ldm4(tmp, b_lane + (uint32_t)(j * 16 * KPADH + kk * 16) * 2);
                bf[2 * j][0] = tmp[0]; bf[2 * j][1] = tmp[1];
                bf[2 * j + 1][0] = tmp[2]; bf[2 * j + 1][1] = tmp[3];
            }
#pragma unroll
            for (int mi = 0; mi < 4; mi++)
#pragma unroll
                for (int ni = 0; ni < 4; ni++)
                    mma16(acc[mi][ni], af[mi], bf[ni]);
        }
        __syncthreads();
        if (kb + 2 < NKB) fill(kb + 2, kb & 1);
    }

#pragma unroll
    for (int mi = 0; mi < 4; mi++) {
        const int r0 = row0 + mwarp * 64 + mi * 16 + g;
#pragma unroll
        for (int ni = 0; ni < 4; ni++) {
            const int cc = col0 + nwarp * 32 + ni * 8 + 2 * tig;
            if constexpr (sizeof(OutT) == 4) {
                *(float2*)((float*)C + (size_t)r0 * Ncols + cc) =
                    make_float2(acc[mi][ni][0], acc[mi][ni][1]);
                *(float2*)((float*)C + (size_t)(r0 + 8) * Ncols + cc) =
                    make_float2(acc[mi][ni][2], acc[mi][ni][3]);
            } else {
                __half2 h0 = __floats2half2_rn(acc[mi][ni][0], acc[mi][ni][1]);
                __half2 h1 = __floats2half2_rn(acc[mi][ni][2], acc[mi][ni][3]);
                *(__half2*)((__half*)C + (size_t)r0 * Ncols + cc) = h0;
                *(__half2*)((__half*)C + (size_t)(r0 + 8) * Ncols + cc) = h1;
            }
        }
    }
}

// ================= pre/post processing =====================================
// pack aug: 8 elements per thread on the x-body (1024 cols), scalar on the tail
__global__ void __launch_bounds__(256)
pack_aug_kernel(const float* __restrict__ x, const float* __restrict__ ev)
{
    // region A: x body, vectorized. NTOK*1024/8 = 2,097,152 threads
    long long vid = (long long)blockIdx.x * blockDim.x + threadIdx.x;
    const long long nvec = (long long)NTOK * DMODEL / 8;
    if (vid < nvec) {
        long long m = vid / (DMODEL / 8);
        int c8 = (int)(vid % (DMODEL / 8)) * 8;
        float4 v0 = *(const float4*)(x + m * DMODEL + c8);
        float4 v1 = *(const float4*)(x + m * DMODEL + c8 + 4);
        __half2* dst = (__half2*)(g_augh + m * KAUG + c8);
        dst[0] = __floats2half2_rn(v0.x, v0.y);
        dst[1] = __floats2half2_rn(v0.z, v0.w);
        dst[2] = __floats2half2_rn(v1.x, v1.y);
        dst[3] = __floats2half2_rn(v1.z, v1.w);
    } else {
        // region B: ev + pad (64 cols per row)
        long long e = vid - nvec;
        if (e >= (long long)NTOK * (KAUG - DMODEL) / 8) return;
        long long m = e / 8;                    // 8 vec8 per row tail
        int c8 = (int)(e % 8) * 8;              // 0..56
        __half2* dst = (__half2*)(g_augh + m * KAUG + DMODEL + c8);
#pragma unroll
        for (int i = 0; i < 4; i++) {
            int c0 = c8 + 2 * i, c1 = c8 + 2 * i + 1;
            float f0 = (c0 < EVDIM) ? ev[m * EVDIM + c0] : 0.f;
            float f1 = (c1 < EVDIM) ? ev[m * EVDIM + c1] : 0.f;
            dst[i] = __floats2half2_rn(f0, f1);
        }
    }
}

__global__ void __launch_bounds__(256)
transpose_kernel(const float* __restrict__ src, __half* __restrict__ dst,
                 int K, int N, int Kp)
{
    __shared__ float tile[32][33];
    const int tx = threadIdx.x & 31, ty = threadIdx.x >> 5;
    const int kb = blockIdx.x * 32, nb = blockIdx.y * 32;
#pragma unroll
    for (int u = 0; u < 4; u++) {
        int kk = kb + ty + u * 8;
        tile[ty + u * 8][tx] = (kk < K) ? src[(size_t)kk * N + nb + tx] : 0.f;
    }
    __syncthreads();
#pragma unroll
    for (int u = 0; u < 4; u++) {
        int n = nb + ty + u * 8;
        dst[(size_t)n * Kp + kb + tx] = __float2half_rn(tile[tx][ty + u * 8]);
    }
}

// causal depthwise conv (d_conv=4) + SiLU, half2: 2 channels per thread
__global__ void __launch_bounds__(256)
conv_silu_kernel(const float* __restrict__ cw, const float* __restrict__ cb)
{
    long long vid = (long long)blockIdx.x * blockDim.x + threadIdx.x;
    if (vid >= (long long)NTOK * DIN / 2) return;
    int chp = (int)(vid & (DIN / 2 - 1));       // channel pair index
    int ch = chp * 2;
    long long tok = vid >> 10;                  // / (DIN/2)
    int l = (int)(tok & (SEQLEN - 1));
    long long tok0 = tok - l;

    float a0 = cb[ch], a1 = cb[ch + 1];
#pragma unroll
    for (int j = 0; j < DCONV; j++) {
        int ls = l - (DCONV - 1) + j;
        if (ls >= 0) {
            __half2 xv = *(const __half2*)(g_xzh + (tok0 + ls) * (size_t)(2 * DIN) + ch);
            float2 xf = __half22float2(xv);
            a0 += cw[ch * DCONV + j] * xf.x;
            a1 += cw[(ch + 1) * DCONV + j] * xf.y;
        }
    }
    *(__half2*)(g_xch + tok * (size_t)DIN + ch) =
        __floats2half2_rn(silu_f(a0), silu_f(a1));
}

__global__ void __launch_bounds__(256)
dt_post_kernel(const float* __restrict__ dtb, const float* __restrict__ Alog)
{
    int idx = blockIdx.x * blockDim.x + threadIdx.x;
    if (idx >= NTOK * NHEADS) return;
    int h = idx & (NHEADS - 1);
    int tok = idx >> 5;
    float v = __half2float(g_BCh[(size_t)tok * NBC + 2 * DIN + h]) + dtb[h];
    float sp = (v > 20.f) ? v : log1pf(__expf(v));
    g_A[idx] = -__expf(Alog[h]) * sp;
}

// ---------------- fused SSD scan (R9-proven: split p, half staging) --------
__global__ void __launch_bounds__(128)
scan_kernel()
{
    __shared__ __half sBh[2][16][72];
    __shared__ __half sCh[2][16][72];
    __shared__ __half sXh[2][16][40];
    __shared__ float  sAv[2][16];
    __shared__ float  sB[16][68];
    __shared__ float  sC[16][68];
    __shared__ float  sX[16][36];
    __shared__ float  sG[16][16];
    __shared__ float  sCum[16];
    __shared__ float  sPart[16 * 4 * 32];

    const int t = threadIdx.x;
    const int bh = blockIdx.x;
    const int bi = bh >> 5, h = bh & 31;
    const int p0 = blockIdx.y * 32;
    const int p = t & 31;
    const int ng = t >> 5;
    const int i4 = ng * 4;
    const size_t headoff = (size_t)h * HEADDIM;

    const uint32_t uBh = smem_u32(sBh), uCh = smem_u32(sCh);
    const uint32_t uXh = smem_u32(sXh), uAv = smem_u32(sAv);

    auto loadChunk = [&](int c, int st) {
        const size_t l0 = (size_t)bi * SEQLEN + c * BLK;
        {
            int r = t >> 3, q = t & 7;
            const size_t rowBC = (l0 + r) * (size_t)NBC + headoff;
            uint32_t so = (uint32_t)(((st * 16 + r) * 72 + q * 8) * 2);
            cp16(uBh + so, g_BCh + rowBC + q * 8);
            cp16(uCh + so, g_BCh + rowBC + DIN + q * 8);
        }
        if (t < 64) {
            int r = t >> 2, q = t & 3;
            uint32_t so = (uint32_t)(((st * 16 + r) * 40 + q * 8) * 2);
            cp16(uXh + so, g_xch + (l0 + r) * (size_t)DIN + headoff + p0 + q * 8);
        }
        if (t < 16)
            cp4(uAv + (uint32_t)((st * 16 + t) * 4), g_A + (l0 + t) * NHEADS + h);
        cp_commit();
    };

    float H[16];
#pragma unroll
    for (int i = 0; i < 16; i++) H[i] = 0.f;

    loadChunk(0, 0);
    for (int c = 0; c < NCHUNK; c++) {
        const int st = c & 1;
        if (c + 1 < NCHUNK) { loadChunk(c + 1, st ^ 1); cp_wait<1>(); }
        else                { cp_wait<0>(); }
        __syncthreads();

#pragma unroll
        for (int u = 0; u < 4; u++) {
            int e = t + u * 128;
            int r = e >> 5, pr = e & 31;
            float2 fb = __half22float2(*(__half2*)&sBh[st][r][pr * 2]);
            float2 fc = __half22float2(*(__half2*)&sCh[st][r][pr * 2]);
            sB[r][2 * pr] = fb.x; sB[r][2 * pr + 1] = fb.y;
            sC[r][2 * pr] = fc.x; sC[r][2 * pr + 1] = fc.y;
        }
#pragma unroll
        for (int u = 0; u < 2; u++) {
            int e = t + u * 128;
            int r = e >> 4, pr = e & 15;
            float2 fx = __half22float2(*(__half2*)&sXh[st][r][pr * 2]);
            sX[r][2 * pr] = fx.x; sX[r][2 * pr + 1] = fx.y;
        }
        if (t < 16) {
            float s = 0.f;
            for (int k = 0; k <= t; k++) s += sAv[st][k];
            sCum[t] = s;
        }
        __syncthreads();
        const float cum15 = sCum[15];
        const size_t l0 = (size_t)bi * SEQLEN + c * BLK;

#pragma unroll
        for (int u = 0; u < 2; u++) {
            int e = t + u * 128;
            int i = e >> 4, j = e & 15;
            float gg = 0.f;
            if (j <= i) {
                float d = 0.f;
#pragma unroll
                for (int n = 0; n < 64; n++) d += sC[i][n] * sB[j][n];
                gg = d * __expf(sCum[i] - sCum[j]);
            }
            sG[i][j] = gg;
        }
        {
            int nb = ng * 16;
#pragma unroll
            for (int i = 0; i < 16; i++) {
                float s = 0.f;
#pragma unroll
                for (int k = 0; k < 16; k++) s += sC[i][nb + k] * H[k];
                sPart[(i * 4 + ng) * 32 + p] = s;
            }
        }
        __syncthreads();

        float yv[4];
#pragma unroll
        for (int r = 0; r < 4; r++) {
            int i = i4 + r;
            float s = 0.f;
#pragma unroll
            for (int j = 0; j < 16; j++) s += sG[i][j] * sX[j][p];
            float off = sPart[(i * 4 + 0) * 32 + p] + sPart[(i * 4 + 1) * 32 + p]
                      + sPart[(i * 4 + 2) * 32 + p] + sPart[(i * 4 + 3) * 32 + p];
            yv[r] = s + __expf(sCum[i]) * off;
        }
        __syncthreads();

#pragma unroll
        for (int r = 0; r < 4; r++) {
            int i = i4 + r;
            sX[i][p] *= __expf(cum15 - sCum[i]);
            float zz = __half2float(
                g_xzh[(l0 + i) * (size_t)(2 * DIN) + DIN + headoff + p0 + p]);
            g_Yzh[(l0 + i) * (size_t)DIN + headoff + p0 + p] =
                __float2half_rn(yv[r] * silu_f(zz));
        }
        __syncthreads();

        {
            float eA = __expf(cum15);
            int nb = ng * 16;
#pragma unroll
            for (int k = 0; k < 16; k++) {
                float s = 0.f;
#pragma unroll
                for (int i = 0; i < 16; i++) s += sB[i][nb + k] * sX[i][p];
                H[k] = eA * H[k] + s;
            }
        }
    }
}

// ---------------- residual + LayerNorm (reads half pre-LN) ----------------
__global__ void __launch_bounds__(256)
ln_kernel(const float* __restrict__ res, const float* __restrict__ gamma,
          const float* __restrict__ beta, float* __restrict__ dout)
{
    const int row = blockIdx.x;
    const int t = threadIdx.x;
    const size_t base = (size_t)row * DMODEL;

    float4 r4 = *(const float4*)(res + base + t * 4);
    __half2 oh0 = *(const __half2*)(g_outh + base + t * 4);
    __half2 oh1 = *(const __half2*)(g_outh + base + t * 4 + 2);
    float2 of0 = __half22float2(oh0), of1 = __half22float2(oh1);
    float h0 = r4.x + of0.x, h1 = r4.y + of0.y, h2 = r4.z + of1.x, h3 = r4.w + of1.y;
    float s = h0 + h1 + h2 + h3;
    float sq = h0 * h0 + h1 * h1 + h2 * h2 + h3 * h3;

    __shared__ float red[2][8];
#pragma unroll
    for (int o = 16; o > 0; o >>= 1) {
        s += __shfl_xor_sync(0xffffffffu, s, o);
        sq += __shfl_xor_sync(0xffffffffu, sq, o);
    }
    int wid = t >> 5, lid = t & 31;
    if (lid == 0) { red[0][wid] = s; red[1][wid] = sq; }
    __syncthreads();
    if (t < 32) {
        s = (t < 8) ? red[0][t] : 0.f;
        sq = (t < 8) ? red[1][t] : 0.f;
#pragma unroll
        for (int o = 4; o > 0; o >>= 1) {
            s += __shfl_xor_sync(0xffffffffu, s, o);
            sq += __shfl_xor_sync(0xffffffffu, sq, o);
        }
        if (t == 0) { red[0][0] = s; red[1][0] = sq; }
    }
    __syncthreads();
    float mu = red[0][0] * (1.f / DMODEL);
    float var = red[1][0] * (1.f / DMODEL) - mu * mu;
    float inv = rsqrtf(var + 1e-5f);

    float4 g4 = *(const float4*)(gamma + t * 4);
    float4 b4 = *(const float4*)(beta + t * 4);
    float4 ov;
    ov.x = (h0 - mu) * inv * g4.x + b4.x;
    ov.y = (h1 - mu) * inv * g4.y + b4.y;
    ov.z = (h2 - mu) * inv * g4.z + b4.z;
    ov.w = (h3 - mu) * inv * g4.w + b4.w;
    *(float4*)(dout + base + t * 4) = ov;
}

// ---------------- launcher ----------------
extern "C" void kernel_launch(void* const* d_in, const int* in_sizes, int n_in,
                              void* d_out, int out_size)
{
    const float* x        = (const float*)d_in[0];
    const float* ev       = (const float*)d_in[1];
    const float* w_in     = (const float*)d_in[2];   // (1040,4096)
    const float* conv_w   = (const float*)d_in[3];
    const float* conv_b   = (const float*)d_in[4];
    const float* A_log    = (const float*)d_in[5];
    const float* w_B      = (const float*)d_in[6];   // (2048,2048)
    const float* w_C      = (const float*)d_in[7];
    const float* w_dt     = (const float*)d_in[8];   // (2048,32)
    const float* b_dt     = (const float*)d_in[9];
    const float* w_out    = (const float*)d_in[10];  // (2048,1024)
    const float* ln_gamma = (const float*)d_in[11];
    const float* ln_beta  = (const float*)d_in[12];
    float* out = (float*)d_out;

    cudaFuncSetAttribute(mma_gemm<__half>, cudaFuncAttributeMaxDynamicSharedMemorySize,
                         GEMM_SMEM);

    __half *p_augh, *p_winth, *p_wbcth, *p_woth, *p_xch, *p_Yzh, *p_xzh, *p_BCh, *p_outh;
    cudaGetSymbolAddress((void**)&p_augh,  g_augh);
    cudaGetSymbolAddress((void**)&p_winth, g_winth);
    cudaGetSymbolAddress((void**)&p_wbcth, g_wbcth);
    cudaGetSymbolAddress((void**)&p_woth,  g_woth);
    cudaGetSymbolAddress((void**)&p_xch,   g_xch);
    cudaGetSymbolAddress((void**)&p_Yzh,   g_Yzh);
    cudaGetSymbolAddress((void**)&p_xzh,   g_xzh);
    cudaGetSymbolAddress((void**)&p_BCh,   g_BCh);
    cudaGetSymbolAddress((void**)&p_outh,  g_outh);

    // launches (my index): 0 pack, 1 t_win, 2 t_wB, 3 t_wC,
    //                      4 GEMM1a, 5 GEMM1b   <- ncu slot 5 hits a GEMM
    {
        long long n = (long long)NTOK * DMODEL / 8 + (long long)NTOK * (KAUG - DMODEL) / 8;
        pack_aug_kernel<<<(unsigned)((n + 255) / 256), 256>>>(x, ev);                 // 0
    }
    transpose_kernel<<<dim3(KAUG / 32, 4096 / 32), 256>>>(w_in, p_winth, 1040, 4096, KAUG); // 1
    transpose_kernel<<<dim3(DIN / 32, DIN / 32), 256>>>(w_B, p_wbcth, DIN, DIN, DIN);       // 2
    transpose_kernel<<<dim3(DIN / 32, DIN / 32), 256>>>(w_C, p_wbcth + (size_t)DIN * DIN,
                                                        DIN, DIN, DIN);                     // 3

    // 4,5) xz = aug @ w_in  split into two N-halves (each 16384 x 2048, K=1088)
    mma_gemm<__half><<<dim3(2048 / BN, NTOK / BM), 256, GEMM_SMEM>>>(
        p_augh, p_winth, p_xzh, KAUG, KAUG / GBK, 4096, 0);
    mma_gemm<__half><<<dim3(2048 / BN, NTOK / BM), 256, GEMM_SMEM>>>(
        p_augh, p_winth, p_xzh, KAUG, KAUG / GBK, 4096, 2048);

    // remaining transposes (needed before GEMM2 / GEMM3)
    transpose_kernel<<<dim3(DIN / 32, 1), 256>>>(w_dt, p_wbcth + (size_t)2 * DIN * DIN,
                                                 DIN, 32, DIN);
    transpose_kernel<<<dim3(DIN / 32, DMODEL / 32), 256>>>(w_out, p_woth, DIN, DMODEL, DIN);

    // xc = silu(conv(x_path)+b) -> half (half2 version)
    {
        long long n = (long long)NTOK * DIN / 2;
        conv_silu_kernel<<<(unsigned)((n + 255) / 256), 256>>>(conv_w, conv_b);
    }
    // [B|C|dt] = xc @ [w_B|w_C|w_dt]  (16384 x 4224, K=2048) -> half
    mma_gemm<__half><<<dim3(NBC / BN, NTOK / BM), 256, GEMM_SMEM>>>(
        p_xch, p_wbcth, p_BCh, DIN, DIN / GBK, NBC, 0);
    // A from dtraw
    dt_post_kernel<<<(NTOK * NHEADS) / 256, 256>>>(b_dt, A_log);
    // scan -> Yz (half)
    scan_kernel<<<dim3(BATCH * NHEADS, 2), 128>>>();
    // out = Yz @ w_out              (16384 x 1024, K=2048) -> half
    mma_gemm<__half><<<dim3(DMODEL / BN, NTOK / BM), 256, GEMM_SMEM>>>(
        p_Yzh, p_woth, p_outh, DIN, DIN / GBK, DMODEL, 0);
    // LayerNorm(residual + out)
    ln_kernel<<<NTOK, 256>>>(x, ln_gamma, ln_beta, out);
}